// round 7
// baseline (speedup 1.0000x reference)
#include <cuda_runtime.h>
#include <cuda_bf16.h>

#define HH 384
#define WW 384
#define BATCH 4
#define CIN 64
#define COUT 64
#define NPIX (BATCH*HH*WW)

// Scratch (no allocations allowed): combined weights + per-pixel route flags.
// g_wcomb layout: [ci][tap][co*2 + path], path 0 = W_low_eff, path 1 = W_high - W_low_eff
__device__ float g_wcomb[64 * 9 * 128];
__device__ unsigned char g_flags[NPIX];

// ---------------------------------------------------------------------------
// Prep 1: compose low-rank path into a single 3x3 kernel; build interleaved
// (low, high-low) weight table in the exact smem staging layout.
// ---------------------------------------------------------------------------
__global__ void prep_weights(const float* __restrict__ high_w,   // (64,64,3,3)
                             const float* __restrict__ low1_w,   // (16,64,3,3)
                             const float* __restrict__ low2_w)   // (64,16,1,1)
{
    int id = blockIdx.x * blockDim.x + threadIdx.x;
    if (id >= 64 * 64 * 9) return;
    int co  = id / 576;
    int rem = id % 576;
    int ci  = rem / 9;
    int tap = rem % 9;
    float wle = 0.0f;
#pragma unroll
    for (int m = 0; m < 16; m++)
        wle += low2_w[co * 16 + m] * low1_w[(m * 64 + ci) * 9 + tap];
    float wh = high_w[(co * 64 + ci) * 9 + tap];
    int base = (ci * 9 + tap) * 128 + co * 2;
    g_wcomb[base + 0] = wle;        // low path
    g_wcomb[base + 1] = wh - wle;   // delta to high path
}

// ---------------------------------------------------------------------------
// Prep 2: route flags. mask_idx / inv_mask_idx are a disjoint partition of all
// N pixel indices, so one pass over N covers every flag deterministically.
// ---------------------------------------------------------------------------
__global__ void prep_flags(const int* __restrict__ mask_idx,
                           const int* __restrict__ inv_idx)
{
    int i = blockIdx.x * blockDim.x + threadIdx.x;
    if (i >= NPIX) return;
    if (i < NPIX / 2) g_flags[mask_idx[i]] = 1;
    else              g_flags[inv_idx[i - NPIX / 2]] = 0;
}

// ---------------------------------------------------------------------------
// Main conv: 8x8 pixel tile per block, 256 threads.
// thread = 16 pixel-groups (4 consecutive-w pixels) x 16 cout-groups (4 couts,
// each with L and D accumulators) -> 32 fp32 accumulators / thread.
// ci processed in chunks of 8; per chunk stage x halo (8x10x10) and the
// weight slice (8*9*128 floats) in shared memory.
// ---------------------------------------------------------------------------
__global__ __launch_bounds__(256)
void conv_main(const float* __restrict__ x, float* __restrict__ out)
{
    __shared__ float xs[8][10][12];                     // [ci][hrow][hcol], padded
    __shared__ __align__(16) float ws[8 * 9 * 128];     // [ci][tap][co*2+path]

    const int b  = blockIdx.z;
    const int h0 = blockIdx.y * 8;
    const int w0 = blockIdx.x * 8;
    const int tid = threadIdx.x;
    const int pg = tid & 15;        // pixel group
    const int cg = tid >> 4;        // cout group (4 real couts)
    const int r  = pg >> 1;         // tile row 0..7
    const int c4 = (pg & 1) * 4;    // tile col base 0 or 4

    float accL[4][4] = {{0.f}};
    float accD[4][4] = {{0.f}};

    for (int ci0 = 0; ci0 < 64; ci0 += 8) {
        // stage weight slice (9216 floats, contiguous) via float4
        {
            const float4* src = (const float4*)(g_wcomb + ci0 * 9 * 128);
            float4* dst = (float4*)ws;
#pragma unroll
            for (int i = 0; i < 9; i++)
                dst[tid + i * 256] = src[tid + i * 256];
        }
        // stage x halo tile: 8 ci x 10 x 10 (zero-padded SAME borders)
        for (int i = tid; i < 800; i += 256) {
            int ci = i / 100;
            int rr = (i % 100) / 10;
            int cc = i % 10;
            int gh = h0 + rr - 1;
            int gw = w0 + cc - 1;
            float v = 0.0f;
            if (gh >= 0 && gh < HH && gw >= 0 && gw < WW)
                v = x[((b * CIN + ci0 + ci) * HH + gh) * WW + gw];
            xs[ci][rr][cc] = v;
        }
        __syncthreads();

        for (int ci = 0; ci < 8; ci++) {
#pragma unroll
            for (int kh = 0; kh < 3; kh++) {
                float xv[6];
#pragma unroll
                for (int i = 0; i < 6; i++)
                    xv[i] = xs[ci][r + kh][c4 + i];
#pragma unroll
                for (int kw = 0; kw < 3; kw++) {
                    const float4* wp =
                        (const float4*)&ws[((ci * 3 + kh) * 3 + kw) * 128 + cg * 8];
                    float4 wA = wp[0];
                    float4 wB = wp[1];
#pragma unroll
                    for (int p = 0; p < 4; p++) {
                        float xval = xv[p + kw];
                        accL[p][0] = fmaf(xval, wA.x, accL[p][0]);
                        accD[p][0] = fmaf(xval, wA.y, accD[p][0]);
                        accL[p][1] = fmaf(xval, wA.z, accL[p][1]);
                        accD[p][1] = fmaf(xval, wA.w, accD[p][1]);
                        accL[p][2] = fmaf(xval, wB.x, accL[p][2]);
                        accD[p][2] = fmaf(xval, wB.y, accD[p][2]);
                        accL[p][3] = fmaf(xval, wB.z, accL[p][3]);
                        accD[p][3] = fmaf(xval, wB.w, accD[p][3]);
                    }
                }
            }
        }
        __syncthreads();
    }

    // epilogue: out = low + flag * (high - low)
    const int hh = h0 + r;
#pragma unroll
    for (int p = 0; p < 4; p++) {
        int wcol = w0 + c4 + p;
        int n = (b * HH + hh) * WW + wcol;
        float sel = g_flags[n] ? 1.0f : 0.0f;
#pragma unroll
        for (int j = 0; j < 4; j++) {
            int co = cg * 4 + j;
            out[((b * COUT + co) * HH + hh) * WW + wcol] =
                fmaf(sel, accD[p][j], accL[p][j]);
        }
    }
}

// ---------------------------------------------------------------------------
// Launch: prep kernels then main conv, all on the capture stream.
// ---------------------------------------------------------------------------
extern "C" void kernel_launch(void* const* d_in, const int* in_sizes, int n_in,
                              void* d_out, int out_size)
{
    const float* x      = (const float*)d_in[0];
    const float* high_w = (const float*)d_in[1];
    const float* low1_w = (const float*)d_in[2];
    const float* low2_w = (const float*)d_in[3];
    const int* mask_idx = (const int*)d_in[4];
    const int* inv_idx  = (const int*)d_in[5];
    float* out = (float*)d_out;

    prep_weights<<<(64 * 64 * 9 + 255) / 256, 256>>>(high_w, low1_w, low2_w);
    prep_flags<<<(NPIX + 255) / 256, 256>>>(mask_idx, inv_idx);

    dim3 grid(WW / 8, HH / 8, BATCH);   // 48 x 48 x 4 = 9216 blocks
    conv_main<<<grid, 256>>>(x, out);
}